// round 11
// baseline (speedup 1.0000x reference)
#include <cuda_runtime.h>

typedef unsigned long long ULL;

__device__ __forceinline__ ULL pk2(float lo, float hi){
  ULL r; asm("mov.b64 %0, {%1,%2};" : "=l"(r) : "f"(lo), "f"(hi)); return r;
}
__device__ __forceinline__ float2 upk(ULL v){
  float2 r; asm("mov.b64 {%0,%1}, %2;" : "=f"(r.x), "=f"(r.y) : "l"(v)); return r;
}
#define FMA2(d,a,bb,c) asm("fma.rn.f32x2 %0, %1, %2, %3;" : "=l"(d) : "l"(a), "l"(bb), "l"(c))
#define MUL2(d,a,bb)   asm("mul.rn.f32x2 %0, %1, %2;"     : "=l"(d) : "l"(a), "l"(bb))
#define ADD2(d,a,bb)   asm("add.rn.f32x2 %0, %1, %2;"     : "=l"(d) : "l"(a), "l"(bb))

constexpr int NX_ = 128, NY_ = 128, NT_ = 64;
constexpr float EPS_ = 1e-5f;

constexpr int OFF_H   = 0;         // h[64][128]
constexpr int OFF_QKV = 8192;      // qkv[192][128]; also ff1 W (8192) + ff2 W (8192)
constexpr int OFF_ATT = 32768;     // att[128][128]; also staged qkv W (12288); out W + out C
constexpr int OFF_AUX = 49152;     // AV partials (3*2048) / LN scratch
constexpr int OFF_PS  = 55296;     // QK row partial sums [16][128]
constexpr int SMEM_FLOATS = 57344; // 229,376 bytes

__device__ __forceinline__ void stage(float* __restrict__ dst,
                                      const float* __restrict__ src,
                                      int n4, int tid)
{
  const float4* s = reinterpret_cast<const float4*>(src);
  float4* d = reinterpret_cast<float4*>(dst);
  for (int i = tid; i < n4; i += 512) d[i] = s[i];
}

// combine the 3 AV sk-quarter partial buffers into the o-slice of head h2
__device__ __forceinline__ void combine_head(float* __restrict__ qkv,
                                             const float* __restrict__ aux, int h2, int tid)
{
  float4* ob = reinterpret_cast<float4*>(qkv + h2*16*128);
  const float4* p1 = reinterpret_cast<const float4*>(aux);
  const float4* p2 = reinterpret_cast<const float4*>(aux + 2048);
  const float4* p3 = reinterpret_cast<const float4*>(aux + 4096);
  float4 o = ob[tid], q1 = p1[tid], q2 = p2[tid], q3 = p3[tid];
  o.x += q1.x + q2.x + q3.x;
  o.y += q1.y + q2.y + q3.y;
  o.z += q1.z + q2.z + q3.z;
  o.w += q1.w + q2.w + q3.w;
  ob[tid] = o;
}

// C[o][s] = act( sum_k A[k][s]*Ws[o*K+k] + Bv[o] ); Ws in SHARED (uniform broadcast reads)
template<int OUT, int K, bool RELU, int TPT>
__device__ __forceinline__ void gemm_sm(const float* __restrict__ A,
                                        const float* __restrict__ Ws,
                                        const float* __restrict__ Bv,
                                        float* __restrict__ C, int tid)
{
  constexpr int NTG = 128/TPT;
  constexpr int NOG = 512/NTG;
  constexpr int TO  = OUT/NOG;
  constexpr int PU  = TPT/2;
  const int tx  = tid & (NTG-1);
  const int g   = tid / NTG;        // warp-uniform
  const int tok = TPT*tx;
  ULL acc[TO][PU];
#pragma unroll
  for (int j=0;j<TO;j++){
    float b = __ldg(Bv + g*TO + j);
    ULL bb = pk2(b,b);
#pragma unroll
    for (int p=0;p<PU;p++) acc[j][p] = bb;
  }
#pragma unroll 2
  for (int k=0;k<K;k+=4){
    ULL a0[PU], a1[PU], a2[PU], a3[PU];
    if (TPT == 4){
      float4 f0 = *reinterpret_cast<const float4*>(A + (k  )*128 + tok);
      float4 f1 = *reinterpret_cast<const float4*>(A + (k+1)*128 + tok);
      float4 f2 = *reinterpret_cast<const float4*>(A + (k+2)*128 + tok);
      float4 f3 = *reinterpret_cast<const float4*>(A + (k+3)*128 + tok);
      a0[0]=pk2(f0.x,f0.y); a0[PU-1]=pk2(f0.z,f0.w);
      a1[0]=pk2(f1.x,f1.y); a1[PU-1]=pk2(f1.z,f1.w);
      a2[0]=pk2(f2.x,f2.y); a2[PU-1]=pk2(f2.z,f2.w);
      a3[0]=pk2(f3.x,f3.y); a3[PU-1]=pk2(f3.z,f3.w);
    } else {
#pragma unroll
      for (int p=0;p<PU;p++){
        a0[p] = *reinterpret_cast<const ULL*>(A + (k  )*128 + tok + 2*p);
        a1[p] = *reinterpret_cast<const ULL*>(A + (k+1)*128 + tok + 2*p);
        a2[p] = *reinterpret_cast<const ULL*>(A + (k+2)*128 + tok + 2*p);
        a3[p] = *reinterpret_cast<const ULL*>(A + (k+3)*128 + tok + 2*p);
      }
    }
#pragma unroll
    for (int j=0;j<TO;j++){
      float4 w = *reinterpret_cast<const float4*>(Ws + (g*TO+j)*K + k);
      ULL w0 = pk2(w.x,w.x), w1 = pk2(w.y,w.y), w2 = pk2(w.z,w.z), w3 = pk2(w.w,w.w);
#pragma unroll
      for (int p=0;p<PU;p++){
        FMA2(acc[j][p], a0[p], w0, acc[j][p]);
        FMA2(acc[j][p], a1[p], w1, acc[j][p]);
        FMA2(acc[j][p], a2[p], w2, acc[j][p]);
        FMA2(acc[j][p], a3[p], w3, acc[j][p]);
      }
    }
  }
#pragma unroll
  for (int j=0;j<TO;j++){
    if (TPT == 4){
      float2 v0 = upk(acc[j][0]);
      float2 v1 = upk(acc[j][PU-1]);
      if (RELU){
        v0.x=fmaxf(v0.x,0.f); v0.y=fmaxf(v0.y,0.f);
        v1.x=fmaxf(v1.x,0.f); v1.y=fmaxf(v1.y,0.f);
      }
      *reinterpret_cast<float4*>(C + (g*TO+j)*128 + tok) = make_float4(v0.x,v0.y,v1.x,v1.y);
    } else {
#pragma unroll
      for (int p=0;p<PU;p++){
        float2 v = upk(acc[j][p]);
        if (RELU){ v.x = fmaxf(v.x,0.f); v.y = fmaxf(v.y,0.f); }
        *reinterpret_cast<float2*>(C + (g*TO+j)*128 + tok + 2*p) = v;
      }
    }
  }
}

// h = LN(h + r), with up to two staging jobs overlapped into pass 1
__device__ __forceinline__ void add_ln(float* __restrict__ h,
                                       const float* __restrict__ r,
                                       const float* __restrict__ gs,
                                       const float* __restrict__ gb,
                                       float* __restrict__ aux, int tid,
                                       float* wdst0 = nullptr, const float* wsrc0 = nullptr, int n40 = 0,
                                       float* wdst1 = nullptr, const float* wsrc1 = nullptr, int n41 = 0)
{
  const int s = tid & 127, g = tid >> 7;
  float sum=0.f, sq=0.f;
#pragma unroll
  for (int d=16*g; d<16*g+16; d++){
    float x = h[d*128+s] + r[d*128+s];
    h[d*128+s] = x;
    sum += x; sq += x*x;
  }
  aux[g*128+s] = sum;
  aux[512 + g*128+s] = sq;
  if (wsrc0) stage(wdst0, wsrc0, n40, tid);
  if (wsrc1) stage(wdst1, wsrc1, n41, tid);
  __syncthreads();
  if (tid < 128){
    float S = aux[tid] + aux[128+tid] + aux[256+tid] + aux[384+tid];
    float Q = aux[512+tid] + aux[640+tid] + aux[768+tid] + aux[896+tid];
    float m = S * (1.f/64.f);
    float inv = rsqrtf(Q * (1.f/64.f) - m*m + EPS_);
    aux[1024+tid] = m;
    aux[1152+tid] = inv;
  }
  __syncthreads();
  {
    float m = aux[1024+s], inv = aux[1152+s];
#pragma unroll
    for (int d=16*g; d<16*g+16; d++){
      h[d*128+s] = (h[d*128+s] - m)*inv*__ldg(gs+d) + __ldg(gb+d);
    }
  }
}

__device__ __forceinline__ float dper(float diff, float L){
  float m = fmodf(diff + 0.5f*L, L);
  if (m < 0.f) m += L;
  return m - 0.5f*L;
}

__global__ void __launch_bounds__(512, 1)
ff_kernel(const int* __restrict__ q_lin_idx, const int* __restrict__ offs,
          const float* __restrict__ coords, const float* __restrict__ vals,
          const float* __restrict__ lg,
          const float* __restrict__ pw, const float* __restrict__ pb,
          const float* __restrict__ qw, const float* __restrict__ qbias,
          const float* __restrict__ ow, const float* __restrict__ obias,
          const float* __restrict__ l1s, const float* __restrict__ l1b,
          const float* __restrict__ f1w, const float* __restrict__ f1b,
          const float* __restrict__ f2w, const float* __restrict__ f2b,
          const float* __restrict__ l2s, const float* __restrict__ l2b,
          const float* __restrict__ hls, const float* __restrict__ hlb,
          const float* __restrict__ h1w, const float* __restrict__ h1b,
          const float* __restrict__ h2w, const float* __restrict__ h2b,
          float* __restrict__ out)
{
  extern __shared__ float sm[];
  float* h    = sm + OFF_H;
  float* qkv  = sm + OFF_QKV;
  float* att  = sm + OFF_ATT;
  float* aux  = sm + OFF_AUX;
  float* ps   = sm + OFF_PS;   // 16x128 row partial sums

  const int tid = threadIdx.x;
  const int b   = blockIdx.x;

  // ---------------- Phase A: gather + input projection (+ stage layer-0 qkv W) ----------------
  {
    const int s = tid & 127, g = tid >> 7;
    int qi = __ldg(q_lin_idx + b);
    int i  = qi >> 13;
    int rr = qi & 8191;
    int j  = rr >> 6;
    int kk = rr & 63;
    int di = __ldg(offs + 3*s), dj = __ldg(offs + 3*s + 1), dk = __ldg(offs + 3*s + 2);
    int I = (i + di) & (NX_-1);
    int J = (j + dj) & (NY_-1);
    int T = min(max(kk + dk, 0), NT_-1);
    int nb = (I << 13) + (J << 6) + T;
    float qx = __ldg(coords + 3*qi), qy = __ldg(coords + 3*qi + 1), qt = __ldg(coords + 3*qi + 2);
    float nx = __ldg(coords + 3*nb), ny = __ldg(coords + 3*nb + 1), nt = __ldg(coords + 3*nb + 2);
    float g0 = expf(__ldg(lg+0)), g1 = expf(__ldg(lg+1)), g2 = expf(__ldg(lg+2));
    float f0 = dper(nx - qx, 2.0f) * g0;
    float f1 = dper(ny - qy, 2.0f) * g1;
    float f2 = (nt - qt) * g2;
    float f3 = __ldg(vals + 3*nb), f4 = __ldg(vals + 3*nb + 1), f5 = __ldg(vals + 3*nb + 2);
#pragma unroll
    for (int d = g*16; d < g*16 + 16; d++){
      float a = __ldg(pb + d);
      a += __ldg(pw + 6*d + 0)*f0 + __ldg(pw + 6*d + 1)*f1 + __ldg(pw + 6*d + 2)*f2
         + __ldg(pw + 6*d + 3)*f3 + __ldg(pw + 6*d + 4)*f4 + __ldg(pw + 6*d + 5)*f5;
      h[d*128 + s] = a;
    }
    stage(att, qw, 12288/4, tid);
  }
  __syncthreads();

  // ---------------- Phase B: 2 transformer layers ----------------
  for (int l = 0; l < 2; l++){
    gemm_sm<192,64,false,4>(h, att, qbias + l*192, qkv, tid);
    __syncthreads();

    for (int hd = 0; hd < 4; hd++){
      // ---- QK^T + fused exp + row partial-sums; also combine previous head's AV partials ----
      {
        const float* qb2 = qkv + (hd*16)*128;
        const float* kb  = qkv + (64 + hd*16)*128;
        const int tx = tid & 31;   // sq tile of 4 (lane-contiguous)
        const int ty = tid >> 5;   // sk tile of 8 (warp-uniform)
        ULL acc[8][2];
        ULL z = pk2(0.f, 0.f);
#pragma unroll
        for (int jj=0;jj<8;jj++){ acc[jj][0]=z; acc[jj][1]=z; }
#pragma unroll 4
        for (int di=0; di<16; di++){
          float4 qf = *reinterpret_cast<const float4*>(qb2 + di*128 + 4*tx);
          ULL q0 = pk2(qf.x,qf.y), q1 = pk2(qf.z,qf.w);
          float4 k0 = *reinterpret_cast<const float4*>(kb + di*128 + 8*ty);
          float4 k1 = *reinterpret_cast<const float4*>(kb + di*128 + 8*ty + 4);
          float kvv[8] = {k0.x,k0.y,k0.z,k0.w,k1.x,k1.y,k1.z,k1.w};
#pragma unroll
          for (int jj=0;jj<8;jj++){
            ULL kd = pk2(kvv[jj], kvv[jj]);
            FMA2(acc[jj][0], q0, kd, acc[jj][0]);
            FMA2(acc[jj][1], q1, kd, acc[jj][1]);
          }
        }
        float4 psum = make_float4(0.f,0.f,0.f,0.f);
#pragma unroll
        for (int jj=0;jj<8;jj++){
          float2 v0 = upk(acc[jj][0]);
          float2 v1 = upk(acc[jj][1]);
          float4 e;
          e.x = __expf(0.25f * v0.x);
          e.y = __expf(0.25f * v0.y);
          e.z = __expf(0.25f * v1.x);
          e.w = __expf(0.25f * v1.y);
          *reinterpret_cast<float4*>(att + (8*ty+jj)*128 + 4*tx) = e;
          psum.x += e.x; psum.y += e.y; psum.z += e.z; psum.w += e.w;
        }
        *reinterpret_cast<float4*>(ps + ty*128 + 4*tx) = psum;
        // combine previous head (disjoint smem regions; no barrier needed)
        if (hd > 0) combine_head(qkv, aux, hd-1, tid);
      }
      __syncthreads();

      // ---- AV with inline rowsum inverse ----
      {
        const int pg = tid & 63;        // sq pair: sq = 2*pg
        const int dq = (tid>>6) & 1;    // dv octet
        const int hf = tid >> 7;        // sk quarter
        const float* vb = qkv + (128 + hd*16 + 8*dq)*128;
        ULL acc[8];
        ULL z = pk2(0.f,0.f);
#pragma unroll
        for (int r2=0;r2<8;r2++) acc[r2]=z;
        for (int sk0 = hf*32; sk0 < hf*32 + 32; sk0 += 4){
          float4 vr[8];
#pragma unroll
          for (int r2=0;r2<8;r2++)
            vr[r2] = *reinterpret_cast<const float4*>(vb + r2*128 + sk0);
          ULL a0 = *reinterpret_cast<const ULL*>(att + (sk0  )*128 + 2*pg);
          ULL a1 = *reinterpret_cast<const ULL*>(att + (sk0+1)*128 + 2*pg);
          ULL a2 = *reinterpret_cast<const ULL*>(att + (sk0+2)*128 + 2*pg);
          ULL a3 = *reinterpret_cast<const ULL*>(att + (sk0+3)*128 + 2*pg);
#pragma unroll
          for (int r2=0;r2<8;r2++){
            FMA2(acc[r2], a0, pk2(vr[r2].x, vr[r2].x), acc[r2]);
            FMA2(acc[r2], a1, pk2(vr[r2].y, vr[r2].y), acc[r2]);
            FMA2(acc[r2], a2, pk2(vr[r2].z, vr[r2].z), acc[r2]);
            FMA2(acc[r2], a3, pk2(vr[r2].w, vr[r2].w), acc[r2]);
          }
        }
        // inline rowsum: sum the 16 QK partials for our 2 sq
        ULL s01 = pk2(0.f,0.f);
#pragma unroll
        for (int r2=0;r2<16;r2++){
          ULL pv = *reinterpret_cast<const ULL*>(ps + r2*128 + 2*pg);
          ADD2(s01, s01, pv);
        }
        float2 sf = upk(s01);
        ULL iv = pk2(1.0f/sf.x, 1.0f/sf.y);
        float* dst = (hf==0) ? (qkv + (hd*16 + 8*dq)*128)
                             : (aux + (hf-1)*2048 + 8*dq*128);
#pragma unroll
        for (int r2=0;r2<8;r2++){
          MUL2(acc[r2], acc[r2], iv);
          *reinterpret_cast<ULL*>(dst + r2*128 + 2*pg) = acc[r2];
        }
      }
      __syncthreads();
    }

    // final combine for head 3 + stage out W
    combine_head(qkv, aux, 3, tid);
    stage(att, ow + l*64*64, 4096/4, tid);
    __syncthreads();

    // out gemm: W staged in att[0:4096), C -> att[4096:12288)
    gemm_sm<64,64,false,2>(qkv, att, obias + l*64, att + 4096, tid);
    __syncthreads();
    add_ln(h, att + 4096, l1s + l*64, l1b + l*64, aux, tid,
           qkv,        f1w + l*128*64, 8192/4,
           qkv + 8192, f2w + l*64*128, 8192/4);
    __syncthreads();
    gemm_sm<128,64,true,2>(h, qkv, f1b + l*128, att, tid);
    __syncthreads();
    gemm_sm<64,128,false,2>(att, qkv + 8192, f2b + l*64, qkv, tid);
    __syncthreads();
    if (l == 0){
      add_ln(h, qkv, l2s, l2b, aux, tid, att, qw + 12288, 12288/4);
    } else {
      add_ln(h, qkv, l2s + 64, l2b + 64, aux, tid);
    }
    __syncthreads();
  }

  // ---------------- Phase C ----------------
  {
    const int d = tid & 63, oc = tid >> 6;
    float s0 = 0.f;
#pragma unroll
    for (int t = oc*16; t < oc*16 + 16; t++) s0 += h[d*128 + t];
    aux[oc*64 + d] = s0;
  }
  __syncthreads();
  if (tid < 64){
    float hm = 0.f;
#pragma unroll
    for (int o2=0;o2<8;o2++) hm += aux[o2*64 + tid];
    aux[512 + tid] = hm * (1.0f/128.0f);
  }
  __syncthreads();
  if (tid < 32){
    float a = aux[512 + tid], c = aux[512 + 32 + tid];
    float sum = a + c, sq = a*a + c*c;
#pragma unroll
    for (int off=16; off; off>>=1){
      sum += __shfl_xor_sync(0xffffffffu, sum, off);
      sq  += __shfl_xor_sync(0xffffffffu, sq,  off);
    }
    if (tid == 0){
      float m = sum * (1.f/64.f);
      aux[576] = m;
      aux[577] = rsqrtf(sq * (1.f/64.f) - m*m + EPS_);
    }
  }
  __syncthreads();
  if (tid < 64){
    float m = aux[576], inv = aux[577];
    aux[640 + tid] = (aux[512+tid] - m)*inv*__ldg(hls+tid) + __ldg(hlb+tid);
  }
  __syncthreads();
  if (tid < 64){
    float acc = __ldg(h1b + tid);
#pragma unroll 8
    for (int k=0;k<64;k++) acc += aux[640+k]*__ldg(h1w + tid*64 + k);
    aux[704 + tid] = 0.5f*acc*(1.0f + erff(acc*0.70710678118654752f));
  }
  __syncthreads();
  if (tid < 3){
    float acc = __ldg(h2b + tid);
#pragma unroll 8
    for (int k=0;k<64;k++) acc += aux[704+k]*__ldg(h2w + tid*64 + k);
    out[b*3 + tid] = acc;
  }
}

extern "C" void kernel_launch(void* const* d_in, const int* in_sizes, int n_in,
                              void* d_out, int out_size)
{
  const int*   qli    = (const int*)  d_in[0];
  const int*   offs   = (const int*)  d_in[1];
  const float* coords = (const float*)d_in[2];
  const float* vals   = (const float*)d_in[3];
  const float* lg     = (const float*)d_in[4];
  const float* pw     = (const float*)d_in[5];
  const float* pb     = (const float*)d_in[6];
  const float* qw     = (const float*)d_in[7];
  const float* qb     = (const float*)d_in[8];
  const float* ow     = (const float*)d_in[9];
  const float* ob     = (const float*)d_in[10];
  const float* l1s    = (const float*)d_in[11];
  const float* l1b    = (const float*)d_in[12];
  const float* f1w    = (const float*)d_in[13];
  const float* f1b    = (const float*)d_in[14];
  const float* f2w    = (const float*)d_in[15];
  const float* f2b    = (const float*)d_in[16];
  const float* l2s    = (const float*)d_in[17];
  const float* l2b    = (const float*)d_in[18];
  const float* hls    = (const float*)d_in[19];
  const float* hlb    = (const float*)d_in[20];
  const float* h1w    = (const float*)d_in[21];
  const float* h1b    = (const float*)d_in[22];
  const float* h2w    = (const float*)d_in[23];
  const float* h2b    = (const float*)d_in[24];
  float* out = (float*)d_out;
  const int B = in_sizes[0];

  cudaFuncSetAttribute(ff_kernel, cudaFuncAttributeMaxDynamicSharedMemorySize,
                       SMEM_FLOATS * (int)sizeof(float));
  ff_kernel<<<B, 512, SMEM_FLOATS * sizeof(float)>>>(
      qli, offs, coords, vals, lg, pw, pb, qw, qb, ow, ob,
      l1s, l1b, f1w, f1b, f2w, f2b, l2s, l2b,
      hls, hlb, h1w, h1b, h2w, h2b, out);
}

// round 13
// speedup vs baseline: 1.0087x; 1.0087x over previous
#include <cuda_runtime.h>

typedef unsigned long long ULL;

__device__ __forceinline__ ULL pk2(float lo, float hi){
  ULL r; asm("mov.b64 %0, {%1,%2};" : "=l"(r) : "f"(lo), "f"(hi)); return r;
}
__device__ __forceinline__ float2 upk(ULL v){
  float2 r; asm("mov.b64 {%0,%1}, %2;" : "=f"(r.x), "=f"(r.y) : "l"(v)); return r;
}
#define FMA2(d,a,bb,c) asm("fma.rn.f32x2 %0, %1, %2, %3;" : "=l"(d) : "l"(a), "l"(bb), "l"(c))
#define MUL2(d,a,bb)   asm("mul.rn.f32x2 %0, %1, %2;"     : "=l"(d) : "l"(a), "l"(bb))

constexpr int NX_ = 128, NY_ = 128, NT_ = 64;
constexpr float EPS_ = 1e-5f;

constexpr int OFF_H   = 0;         // h[64][128]
constexpr int OFF_QKV = 8192;      // qkv[192][128]; also ff1 W (8192) + ff2 W (8192)
constexpr int OFF_ATT = 32768;     // att bf16x2 [128][64 u32] (32KB); also staged qkv W; out W + C; ff hidden
constexpr int OFF_AUX = 49152;     // AV partials (3*2048) / QK row-psum / LN scratch
constexpr int OFF_RS  = 55296;     // row sums
constexpr int SMEM_FLOATS = 55808; // 223,232 bytes

__device__ __forceinline__ void stage(float* __restrict__ dst,
                                      const float* __restrict__ src,
                                      int n4, int tid)
{
  const float4* s = reinterpret_cast<const float4*>(src);
  float4* d = reinterpret_cast<float4*>(dst);
  for (int i = tid; i < n4; i += 512) d[i] = s[i];
}

// C[o][s] = act( sum_k A[k][s]*Ws[o*K+k] + Bv[o] ); Ws in SHARED (uniform broadcast reads)
template<int OUT, int K, bool RELU, int TPT>
__device__ __forceinline__ void gemm_sm(const float* __restrict__ A,
                                        const float* __restrict__ Ws,
                                        const float* __restrict__ Bv,
                                        float* __restrict__ C, int tid)
{
  constexpr int NTG = 128/TPT;
  constexpr int NOG = 512/NTG;
  constexpr int TO  = OUT/NOG;
  constexpr int PU  = TPT/2;
  const int tx  = tid & (NTG-1);
  const int g   = tid / NTG;        // warp-uniform
  const int tok = TPT*tx;
  ULL acc[TO][PU];
#pragma unroll
  for (int j=0;j<TO;j++){
    float b = __ldg(Bv + g*TO + j);
    ULL bb = pk2(b,b);
#pragma unroll
    for (int p=0;p<PU;p++) acc[j][p] = bb;
  }
#pragma unroll 2
  for (int k=0;k<K;k+=4){
    ULL a0[PU], a1[PU], a2[PU], a3[PU];
    if (TPT == 4){
      float4 f0 = *reinterpret_cast<const float4*>(A + (k  )*128 + tok);
      float4 f1 = *reinterpret_cast<const float4*>(A + (k+1)*128 + tok);
      float4 f2 = *reinterpret_cast<const float4*>(A + (k+2)*128 + tok);
      float4 f3 = *reinterpret_cast<const float4*>(A + (k+3)*128 + tok);
      a0[0]=pk2(f0.x,f0.y); a0[PU-1]=pk2(f0.z,f0.w);
      a1[0]=pk2(f1.x,f1.y); a1[PU-1]=pk2(f1.z,f1.w);
      a2[0]=pk2(f2.x,f2.y); a2[PU-1]=pk2(f2.z,f2.w);
      a3[0]=pk2(f3.x,f3.y); a3[PU-1]=pk2(f3.z,f3.w);
    } else {
#pragma unroll
      for (int p=0;p<PU;p++){
        a0[p] = *reinterpret_cast<const ULL*>(A + (k  )*128 + tok + 2*p);
        a1[p] = *reinterpret_cast<const ULL*>(A + (k+1)*128 + tok + 2*p);
        a2[p] = *reinterpret_cast<const ULL*>(A + (k+2)*128 + tok + 2*p);
        a3[p] = *reinterpret_cast<const ULL*>(A + (k+3)*128 + tok + 2*p);
      }
    }
#pragma unroll
    for (int j=0;j<TO;j++){
      float4 w = *reinterpret_cast<const float4*>(Ws + (g*TO+j)*K + k);
      ULL w0 = pk2(w.x,w.x), w1 = pk2(w.y,w.y), w2 = pk2(w.z,w.z), w3 = pk2(w.w,w.w);
#pragma unroll
      for (int p=0;p<PU;p++){
        FMA2(acc[j][p], a0[p], w0, acc[j][p]);
        FMA2(acc[j][p], a1[p], w1, acc[j][p]);
        FMA2(acc[j][p], a2[p], w2, acc[j][p]);
        FMA2(acc[j][p], a3[p], w3, acc[j][p]);
      }
    }
  }
#pragma unroll
  for (int j=0;j<TO;j++){
    if (TPT == 4){
      float2 v0 = upk(acc[j][0]);
      float2 v1 = upk(acc[j][PU-1]);
      if (RELU){
        v0.x=fmaxf(v0.x,0.f); v0.y=fmaxf(v0.y,0.f);
        v1.x=fmaxf(v1.x,0.f); v1.y=fmaxf(v1.y,0.f);
      }
      *reinterpret_cast<float4*>(C + (g*TO+j)*128 + tok) = make_float4(v0.x,v0.y,v1.x,v1.y);
    } else {
#pragma unroll
      for (int p=0;p<PU;p++){
        float2 v = upk(acc[j][p]);
        if (RELU){ v.x = fmaxf(v.x,0.f); v.y = fmaxf(v.y,0.f); }
        *reinterpret_cast<float2*>(C + (g*TO+j)*128 + tok + 2*p) = v;
      }
    }
  }
}

// h = LN(h + r), with up to two staging jobs overlapped into pass 1
__device__ __forceinline__ void add_ln(float* __restrict__ h,
                                       const float* __restrict__ r,
                                       const float* __restrict__ gs,
                                       const float* __restrict__ gb,
                                       float* __restrict__ aux, int tid,
                                       float* wdst0 = nullptr, const float* wsrc0 = nullptr, int n40 = 0,
                                       float* wdst1 = nullptr, const float* wsrc1 = nullptr, int n41 = 0)
{
  const int s = tid & 127, g = tid >> 7;
  float sum=0.f, sq=0.f;
#pragma unroll
  for (int d=16*g; d<16*g+16; d++){
    float x = h[d*128+s] + r[d*128+s];
    h[d*128+s] = x;
    sum += x; sq += x*x;
  }
  aux[g*128+s] = sum;
  aux[512 + g*128+s] = sq;
  if (wsrc0) stage(wdst0, wsrc0, n40, tid);
  if (wsrc1) stage(wdst1, wsrc1, n41, tid);
  __syncthreads();
  if (tid < 128){
    float S = aux[tid] + aux[128+tid] + aux[256+tid] + aux[384+tid];
    float Q = aux[512+tid] + aux[640+tid] + aux[768+tid] + aux[896+tid];
    float m = S * (1.f/64.f);
    float inv = rsqrtf(Q * (1.f/64.f) - m*m + EPS_);
    aux[1024+tid] = m;
    aux[1152+tid] = inv;
  }
  __syncthreads();
  {
    float m = aux[1024+s], inv = aux[1152+s];
#pragma unroll
    for (int d=16*g; d<16*g+16; d++){
      h[d*128+s] = (h[d*128+s] - m)*inv*__ldg(gs+d) + __ldg(gb+d);
    }
  }
}

__device__ __forceinline__ float dper(float diff, float L){
  float m = fmodf(diff + 0.5f*L, L);
  if (m < 0.f) m += L;
  return m - 0.5f*L;
}

__global__ void __launch_bounds__(512, 1)
ff_kernel(const int* __restrict__ q_lin_idx, const int* __restrict__ offs,
          const float* __restrict__ coords, const float* __restrict__ vals,
          const float* __restrict__ lg,
          const float* __restrict__ pw, const float* __restrict__ pb,
          const float* __restrict__ qw, const float* __restrict__ qbias,
          const float* __restrict__ ow, const float* __restrict__ obias,
          const float* __restrict__ l1s, const float* __restrict__ l1b,
          const float* __restrict__ f1w, const float* __restrict__ f1b,
          const float* __restrict__ f2w, const float* __restrict__ f2b,
          const float* __restrict__ l2s, const float* __restrict__ l2b,
          const float* __restrict__ hls, const float* __restrict__ hlb,
          const float* __restrict__ h1w, const float* __restrict__ h1b,
          const float* __restrict__ h2w, const float* __restrict__ h2b,
          float* __restrict__ out)
{
  extern __shared__ float sm[];
  float* h    = sm + OFF_H;
  float* qkv  = sm + OFF_QKV;
  float* att  = sm + OFF_ATT;
  float* aux  = sm + OFF_AUX;
  float* rs   = sm + OFF_RS;
  unsigned* attb = reinterpret_cast<unsigned*>(att);  // bf16x2 att [sk][64]

  const int tid = threadIdx.x;
  const int b   = blockIdx.x;

  // ---------------- Phase A: gather + input projection (+ stage layer-0 qkv W) ----------------
  {
    const int s = tid & 127, g = tid >> 7;
    int qi = __ldg(q_lin_idx + b);
    int i  = qi >> 13;
    int rr = qi & 8191;
    int j  = rr >> 6;
    int kk = rr & 63;
    int di = __ldg(offs + 3*s), dj = __ldg(offs + 3*s + 1), dk = __ldg(offs + 3*s + 2);
    int I = (i + di) & (NX_-1);
    int J = (j + dj) & (NY_-1);
    int T = min(max(kk + dk, 0), NT_-1);
    int nb = (I << 13) + (J << 6) + T;
    float qx = __ldg(coords + 3*qi), qy = __ldg(coords + 3*qi + 1), qt = __ldg(coords + 3*qi + 2);
    float nx = __ldg(coords + 3*nb), ny = __ldg(coords + 3*nb + 1), nt = __ldg(coords + 3*nb + 2);
    float g0 = expf(__ldg(lg+0)), g1 = expf(__ldg(lg+1)), g2 = expf(__ldg(lg+2));
    float f0 = dper(nx - qx, 2.0f) * g0;
    float f1 = dper(ny - qy, 2.0f) * g1;
    float f2 = (nt - qt) * g2;
    float f3 = __ldg(vals + 3*nb), f4 = __ldg(vals + 3*nb + 1), f5 = __ldg(vals + 3*nb + 2);
#pragma unroll
    for (int d = g*16; d < g*16 + 16; d++){
      float a = __ldg(pb + d);
      a += __ldg(pw + 6*d + 0)*f0 + __ldg(pw + 6*d + 1)*f1 + __ldg(pw + 6*d + 2)*f2
         + __ldg(pw + 6*d + 3)*f3 + __ldg(pw + 6*d + 4)*f4 + __ldg(pw + 6*d + 5)*f5;
      h[d*128 + s] = a;
    }
    stage(att, qw, 12288/4, tid);
  }
  __syncthreads();

  // ---------------- Phase B: 2 transformer layers ----------------
  for (int l = 0; l < 2; l++){
    gemm_sm<192,64,false,4>(h, att, qbias + l*192, qkv, tid);
    __syncthreads();

    for (int hd = 0; hd < 4; hd++){
      // ---- QK^T + fused exp + row partial-sums; att stored bf16x2 ----
      {
        const float* qb2 = qkv + (hd*16)*128;
        const float* kb  = qkv + (64 + hd*16)*128;
        const int tx = tid & 31;   // sq tile of 4 (lane-contiguous)
        const int ty = tid >> 5;   // sk tile of 8 (warp-uniform)
        ULL acc[8][2];
        ULL z = pk2(0.f, 0.f);
#pragma unroll
        for (int jj=0;jj<8;jj++){ acc[jj][0]=z; acc[jj][1]=z; }
#pragma unroll 4
        for (int di=0; di<16; di++){
          float4 qf = *reinterpret_cast<const float4*>(qb2 + di*128 + 4*tx);
          ULL q0 = pk2(qf.x,qf.y), q1 = pk2(qf.z,qf.w);
          float4 k0 = *reinterpret_cast<const float4*>(kb + di*128 + 8*ty);
          float4 k1 = *reinterpret_cast<const float4*>(kb + di*128 + 8*ty + 4);
          float kvv[8] = {k0.x,k0.y,k0.z,k0.w,k1.x,k1.y,k1.z,k1.w};
#pragma unroll
          for (int jj=0;jj<8;jj++){
            ULL kd = pk2(kvv[jj], kvv[jj]);
            FMA2(acc[jj][0], q0, kd, acc[jj][0]);
            FMA2(acc[jj][1], q1, kd, acc[jj][1]);
          }
        }
        float4 psum = make_float4(0.f,0.f,0.f,0.f);
#pragma unroll
        for (int jj=0;jj<8;jj++){
          float2 v0 = upk(acc[jj][0]);
          float2 v1 = upk(acc[jj][1]);
          float e0 = __expf(0.25f * v0.x);
          float e1 = __expf(0.25f * v0.y);
          float e2 = __expf(0.25f * v1.x);
          float e3 = __expf(0.25f * v1.y);
          unsigned p0, p1;
          asm("cvt.rn.bf16x2.f32 %0, %1, %2;" : "=r"(p0) : "f"(e1), "f"(e0));
          asm("cvt.rn.bf16x2.f32 %0, %1, %2;" : "=r"(p1) : "f"(e3), "f"(e2));
          *reinterpret_cast<uint2*>(attb + (8*ty+jj)*64 + 2*tx) = make_uint2(p0, p1);
          psum.x += e0; psum.y += e1; psum.z += e2; psum.w += e3;
        }
        *reinterpret_cast<float4*>(aux + ty*128 + 4*tx) = psum;
      }
      __syncthreads();

      // ---- fold 16 row partials -> rowsum ----
      if (tid < 128){
        float s0 = 0.f;
#pragma unroll
        for (int r2=0;r2<16;r2++) s0 += aux[r2*128 + tid];
        rs[tid] = s0;
      }
      __syncthreads();

      // ---- AV: bf16x2 att loads, fp32 math ----
      {
        const int pg = tid & 63;        // sq pair: sq = 2*pg
        const int dq = (tid>>6) & 1;    // dv octet
        const int hf = tid >> 7;        // sk quarter
        const float* vb = qkv + (128 + hd*16 + 8*dq)*128;
        ULL acc[8];
        ULL z = pk2(0.f,0.f);
#pragma unroll
        for (int r2=0;r2<8;r2++) acc[r2]=z;
        for (int sk0 = hf*32; sk0 < hf*32 + 32; sk0 += 4){
          float4 vr[8];
#pragma unroll
          for (int r2=0;r2<8;r2++)
            vr[r2] = *reinterpret_cast<const float4*>(vb + r2*128 + sk0);
          unsigned u0 = attb[(sk0  )*64 + pg];
          unsigned u1 = attb[(sk0+1)*64 + pg];
          unsigned u2 = attb[(sk0+2)*64 + pg];
          unsigned u3 = attb[(sk0+3)*64 + pg];
          ULL a0 = pk2(__uint_as_float(u0 << 16), __uint_as_float(u0 & 0xFFFF0000u));
          ULL a1 = pk2(__uint_as_float(u1 << 16), __uint_as_float(u1 & 0xFFFF0000u));
          ULL a2 = pk2(__uint_as_float(u2 << 16), __uint_as_float(u2 & 0xFFFF0000u));
          ULL a3 = pk2(__uint_as_float(u3 << 16), __uint_as_float(u3 & 0xFFFF0000u));
#pragma unroll
          for (int r2=0;r2<8;r2++){
            FMA2(acc[r2], a0, pk2(vr[r2].x, vr[r2].x), acc[r2]);
            FMA2(acc[r2], a1, pk2(vr[r2].y, vr[r2].y), acc[r2]);
            FMA2(acc[r2], a2, pk2(vr[r2].z, vr[r2].z), acc[r2]);
            FMA2(acc[r2], a3, pk2(vr[r2].w, vr[r2].w), acc[r2]);
          }
        }
        ULL sv = *reinterpret_cast<const ULL*>(rs + 2*pg);
        float2 sf = upk(sv);
        ULL iv = pk2(1.0f/sf.x, 1.0f/sf.y);
        float* dst = (hf==0) ? (qkv + (hd*16 + 8*dq)*128)
                             : (aux + (hf-1)*2048 + 8*dq*128);
#pragma unroll
        for (int r2=0;r2<8;r2++){
          MUL2(acc[r2], acc[r2], iv);
          *reinterpret_cast<ULL*>(dst + r2*128 + 2*pg) = acc[r2];
        }
      }
      __syncthreads();

      // ---- combine sk-quarter partials (+ stage out W on last head) ----
      {
        float4* ob = reinterpret_cast<float4*>(qkv + hd*16*128);
        const float4* p1 = reinterpret_cast<const float4*>(aux);
        const float4* p2 = reinterpret_cast<const float4*>(aux + 2048);
        const float4* p3 = reinterpret_cast<const float4*>(aux + 4096);
        float4 o = ob[tid], q1 = p1[tid], q2 = p2[tid], q3 = p3[tid];
        o.x += q1.x + q2.x + q3.x;
        o.y += q1.y + q2.y + q3.y;
        o.z += q1.z + q2.z + q3.z;
        o.w += q1.w + q2.w + q3.w;
        ob[tid] = o;
        if (hd == 3) stage(att, ow + l*64*64, 4096/4, tid);
      }
      __syncthreads();
    }

    // out gemm: W in att[0:4096), C -> att[4096:12288)
    gemm_sm<64,64,false,2>(qkv, att, obias + l*64, att + 4096, tid);
    __syncthreads();
    add_ln(h, att + 4096, l1s + l*64, l1b + l*64, aux, tid,
           qkv,        f1w + l*128*64, 8192/4,
           qkv + 8192, f2w + l*64*128, 8192/4);
    __syncthreads();
    gemm_sm<128,64,true,2>(h, qkv, f1b + l*128, att, tid);
    __syncthreads();
    gemm_sm<64,128,false,2>(att, qkv + 8192, f2b + l*64, qkv, tid);
    __syncthreads();
    if (l == 0){
      add_ln(h, qkv, l2s, l2b, aux, tid, att, qw + 12288, 12288/4);
    } else {
      add_ln(h, qkv, l2s + 64, l2b + 64, aux, tid);
    }
    __syncthreads();
  }

  // ---------------- Phase C ----------------
  {
    const int d = tid & 63, oc = tid >> 6;
    float s0 = 0.f;
#pragma unroll
    for (int t = oc*16; t < oc*16 + 16; t++) s0 += h[d*128 + t];
    aux[oc*64 + d] = s0;
  }
  __syncthreads();
  if (tid < 64){
    float hm = 0.f;
#pragma unroll
    for (int o2=0;o2<8;o2++) hm += aux[o2*64 + tid];
    aux[512 + tid] = hm * (1.0f/128.0f);
  }
  __syncthreads();
  if (tid < 32){
    float a = aux[512 + tid], c = aux[512 + 32 + tid];
    float sum = a + c, sq = a*a + c*c;
#pragma unroll
    for (int off=16; off; off>>=1){
      sum += __shfl_xor_sync(0xffffffffu, sum, off);
      sq  += __shfl_xor_sync(0xffffffffu, sq,  off);
    }
    if (tid == 0){
      float m = sum * (1.f/64.f);
      aux[576] = m;
      aux[577] = rsqrtf(sq * (1.f/64.f) - m*m + EPS_);
    }
  }
  __syncthreads();
  if (tid < 64){
    float m = aux[576], inv = aux[577];
    aux[640 + tid] = (aux[512+tid] - m)*inv*__ldg(hls+tid) + __ldg(hlb+tid);
  }
  __syncthreads();
  if (tid < 64){
    float acc = __ldg(h1b + tid);
#pragma unroll 8
    for (int k=0;k<64;k++) acc += aux[640+k]*__ldg(h1w + tid*64 + k);
    aux[704 + tid] = 0.5f*acc*(1.0f + erff(acc*0.70710678118654752f));
  }
  __syncthreads();
  if (tid < 3){
    float acc = __ldg(h2b + tid);
#pragma unroll 8
    for (int k=0;k<64;k++) acc += aux[704+k]*__ldg(h2w + tid*64 + k);
    out[b*3 + tid] = acc;
  }
}

extern "C" void kernel_launch(void* const* d_in, const int* in_sizes, int n_in,
                              void* d_out, int out_size)
{
  const int*   qli    = (const int*)  d_in[0];
  const int*   offs   = (const int*)  d_in[1];
  const float* coords = (const float*)d_in[2];
  const float* vals   = (const float*)d_in[3];
  const float* lg     = (const float*)d_in[4];
  const float* pw     = (const float*)d_in[5];
  const float* pb     = (const float*)d_in[6];
  const float* qw     = (const float*)d_in[7];
  const float* qb     = (const float*)d_in[8];
  const float* ow     = (const float*)d_in[9];
  const float* ob     = (const float*)d_in[10];
  const float* l1s    = (const float*)d_in[11];
  const float* l1b    = (const float*)d_in[12];
  const float* f1w    = (const float*)d_in[13];
  const float* f1b    = (const float*)d_in[14];
  const float* f2w    = (const float*)d_in[15];
  const float* f2b    = (const float*)d_in[16];
  const float* l2s    = (const float*)d_in[17];
  const float* l2b    = (const float*)d_in[18];
  const float* hls    = (const float*)d_in[19];
  const float* hlb    = (const float*)d_in[20];
  const float* h1w    = (const float*)d_in[21];
  const float* h1b    = (const float*)d_in[22];
  const float* h2w    = (const float*)d_in[23];
  const float* h2b    = (const float*)d_in[24];
  float* out = (float*)d_out;
  const int B = in_sizes[0];

  cudaFuncSetAttribute(ff_kernel, cudaFuncAttributeMaxDynamicSharedMemorySize,
                       SMEM_FLOATS * (int)sizeof(float));
  ff_kernel<<<B, 512, SMEM_FLOATS * sizeof(float)>>>(
      qli, offs, coords, vals, lg, pw, pb, qw, qb, ow, ob,
      l1s, l1b, f1w, f1b, f2w, f2b, l2s, l2b,
      hls, hlb, h1w, h1b, h2w, h2b, out);
}

// round 15
// speedup vs baseline: 1.0182x; 1.0094x over previous
#include <cuda_runtime.h>

typedef unsigned long long ULL;

__device__ __forceinline__ ULL pk2(float lo, float hi){
  ULL r; asm("mov.b64 %0, {%1,%2};" : "=l"(r) : "f"(lo), "f"(hi)); return r;
}
__device__ __forceinline__ float2 upk(ULL v){
  float2 r; asm("mov.b64 {%0,%1}, %2;" : "=f"(r.x), "=f"(r.y) : "l"(v)); return r;
}
#define FMA2(d,a,bb,c) asm("fma.rn.f32x2 %0, %1, %2, %3;" : "=l"(d) : "l"(a), "l"(bb), "l"(c))
#define MUL2(d,a,bb)   asm("mul.rn.f32x2 %0, %1, %2;"     : "=l"(d) : "l"(a), "l"(bb))

constexpr int NX_ = 128, NY_ = 128, NT_ = 64;
constexpr float EPS_ = 1e-5f;

constexpr int OFF_H   = 0;         // h[64][128]
constexpr int OFF_QKV = 8192;      // qkv[192][128]; also ff1 W (8192) + ff2 W (8192)
constexpr int OFF_ATT = 32768;     // att bf16 DOUBLE buffer (2x4096 fl); staged qkv W; out W + C; ff hidden
constexpr int OFF_AUX = 49152;     // AV partials (3*2048) / LN scratch
constexpr int OFF_RS  = 55296;     // 128 row sums
constexpr int OFF_PS  = 55808;     // QK row partial sums [16][128]
constexpr int SMEM_FLOATS = 57856; // 231,424 bytes (max 232,448)

__device__ __forceinline__ void stage(float* __restrict__ dst,
                                      const float* __restrict__ src,
                                      int n4, int tid)
{
  const float4* s = reinterpret_cast<const float4*>(src);
  float4* d = reinterpret_cast<float4*>(dst);
  for (int i = tid; i < n4; i += 512) d[i] = s[i];
}

// QK^T + fused exp + row partial sums; att stored bf16x2 into attbuf
__device__ __forceinline__ void qk_head(const float* __restrict__ qkv,
                                        unsigned* __restrict__ attbuf,
                                        float* __restrict__ ps, int hd, int tid)
{
  const float* qb2 = qkv + (hd*16)*128;
  const float* kb  = qkv + (64 + hd*16)*128;
  const int tx = tid & 31;   // sq tile of 4 (lane-contiguous)
  const int ty = tid >> 5;   // sk tile of 8 (warp-uniform)
  ULL acc[8][2];
  ULL z = pk2(0.f, 0.f);
#pragma unroll
  for (int jj=0;jj<8;jj++){ acc[jj][0]=z; acc[jj][1]=z; }
#pragma unroll 4
  for (int di=0; di<16; di++){
    float4 qf = *reinterpret_cast<const float4*>(qb2 + di*128 + 4*tx);
    ULL q0 = pk2(qf.x,qf.y), q1 = pk2(qf.z,qf.w);
    float4 k0 = *reinterpret_cast<const float4*>(kb + di*128 + 8*ty);
    float4 k1 = *reinterpret_cast<const float4*>(kb + di*128 + 8*ty + 4);
    float kvv[8] = {k0.x,k0.y,k0.z,k0.w,k1.x,k1.y,k1.z,k1.w};
#pragma unroll
    for (int jj=0;jj<8;jj++){
      ULL kd = pk2(kvv[jj], kvv[jj]);
      FMA2(acc[jj][0], q0, kd, acc[jj][0]);
      FMA2(acc[jj][1], q1, kd, acc[jj][1]);
    }
  }
  float4 psum = make_float4(0.f,0.f,0.f,0.f);
#pragma unroll
  for (int jj=0;jj<8;jj++){
    float2 v0 = upk(acc[jj][0]);
    float2 v1 = upk(acc[jj][1]);
    float e0 = __expf(0.25f * v0.x);
    float e1 = __expf(0.25f * v0.y);
    float e2 = __expf(0.25f * v1.x);
    float e3 = __expf(0.25f * v1.y);
    unsigned p0, p1;
    asm("cvt.rn.bf16x2.f32 %0, %1, %2;" : "=r"(p0) : "f"(e1), "f"(e0));
    asm("cvt.rn.bf16x2.f32 %0, %1, %2;" : "=r"(p1) : "f"(e3), "f"(e2));
    *reinterpret_cast<uint2*>(attbuf + (8*ty+jj)*64 + 2*tx) = make_uint2(p0, p1);
    psum.x += e0; psum.y += e1; psum.z += e2; psum.w += e3;
  }
  *reinterpret_cast<float4*>(ps + ty*128 + 4*tx) = psum;
}

// AV for head hd: reads attbuf (bf16x2) + rs; writes o-slice (hf0) / aux partials
__device__ __forceinline__ void av_head(float* __restrict__ qkv,
                                        const unsigned* __restrict__ attbuf,
                                        const float* __restrict__ rs,
                                        float* __restrict__ aux, int hd, int tid)
{
  const int pg = tid & 63;        // sq pair: sq = 2*pg
  const int dq = (tid>>6) & 1;    // dv octet
  const int hf = tid >> 7;        // sk quarter
  const float* vb = qkv + (128 + hd*16 + 8*dq)*128;
  ULL acc[8];
  ULL z = pk2(0.f,0.f);
#pragma unroll
  for (int r2=0;r2<8;r2++) acc[r2]=z;
  for (int sk0 = hf*32; sk0 < hf*32 + 32; sk0 += 4){
    float4 vr[8];
#pragma unroll
    for (int r2=0;r2<8;r2++)
      vr[r2] = *reinterpret_cast<const float4*>(vb + r2*128 + sk0);
    unsigned u0 = attbuf[(sk0  )*64 + pg];
    unsigned u1 = attbuf[(sk0+1)*64 + pg];
    unsigned u2 = attbuf[(sk0+2)*64 + pg];
    unsigned u3 = attbuf[(sk0+3)*64 + pg];
    ULL a0 = pk2(__uint_as_float(u0 << 16), __uint_as_float(u0 & 0xFFFF0000u));
    ULL a1 = pk2(__uint_as_float(u1 << 16), __uint_as_float(u1 & 0xFFFF0000u));
    ULL a2 = pk2(__uint_as_float(u2 << 16), __uint_as_float(u2 & 0xFFFF0000u));
    ULL a3 = pk2(__uint_as_float(u3 << 16), __uint_as_float(u3 & 0xFFFF0000u));
#pragma unroll
    for (int r2=0;r2<8;r2++){
      FMA2(acc[r2], a0, pk2(vr[r2].x, vr[r2].x), acc[r2]);
      FMA2(acc[r2], a1, pk2(vr[r2].y, vr[r2].y), acc[r2]);
      FMA2(acc[r2], a2, pk2(vr[r2].z, vr[r2].z), acc[r2]);
      FMA2(acc[r2], a3, pk2(vr[r2].w, vr[r2].w), acc[r2]);
    }
  }
  ULL sv = *reinterpret_cast<const ULL*>(rs + 2*pg);
  float2 sf = upk(sv);
  ULL iv = pk2(1.0f/sf.x, 1.0f/sf.y);
  float* dst = (hf==0) ? (qkv + (hd*16 + 8*dq)*128)
                       : (aux + (hf-1)*2048 + 8*dq*128);
#pragma unroll
  for (int r2=0;r2<8;r2++){
    MUL2(acc[r2], acc[r2], iv);
    *reinterpret_cast<ULL*>(dst + r2*128 + 2*pg) = acc[r2];
  }
}

// C[o][s] = act( sum_k A[k][s]*Ws[o*K+k] + Bv[o] ); Ws in SHARED (uniform broadcast reads)
template<int OUT, int K, bool RELU, int TPT>
__device__ __forceinline__ void gemm_sm(const float* __restrict__ A,
                                        const float* __restrict__ Ws,
                                        const float* __restrict__ Bv,
                                        float* __restrict__ C, int tid)
{
  constexpr int NTG = 128/TPT;
  constexpr int NOG = 512/NTG;
  constexpr int TO  = OUT/NOG;
  constexpr int PU  = TPT/2;
  const int tx  = tid & (NTG-1);
  const int g   = tid / NTG;        // warp-uniform
  const int tok = TPT*tx;
  ULL acc[TO][PU];
#pragma unroll
  for (int j=0;j<TO;j++){
    float b = __ldg(Bv + g*TO + j);
    ULL bb = pk2(b,b);
#pragma unroll
    for (int p=0;p<PU;p++) acc[j][p] = bb;
  }
#pragma unroll 2
  for (int k=0;k<K;k+=4){
    ULL a0[PU], a1[PU], a2[PU], a3[PU];
    if (TPT == 4){
      float4 f0 = *reinterpret_cast<const float4*>(A + (k  )*128 + tok);
      float4 f1 = *reinterpret_cast<const float4*>(A + (k+1)*128 + tok);
      float4 f2 = *reinterpret_cast<const float4*>(A + (k+2)*128 + tok);
      float4 f3 = *reinterpret_cast<const float4*>(A + (k+3)*128 + tok);
      a0[0]=pk2(f0.x,f0.y); a0[PU-1]=pk2(f0.z,f0.w);
      a1[0]=pk2(f1.x,f1.y); a1[PU-1]=pk2(f1.z,f1.w);
      a2[0]=pk2(f2.x,f2.y); a2[PU-1]=pk2(f2.z,f2.w);
      a3[0]=pk2(f3.x,f3.y); a3[PU-1]=pk2(f3.z,f3.w);
    } else {
#pragma unroll
      for (int p=0;p<PU;p++){
        a0[p] = *reinterpret_cast<const ULL*>(A + (k  )*128 + tok + 2*p);
        a1[p] = *reinterpret_cast<const ULL*>(A + (k+1)*128 + tok + 2*p);
        a2[p] = *reinterpret_cast<const ULL*>(A + (k+2)*128 + tok + 2*p);
        a3[p] = *reinterpret_cast<const ULL*>(A + (k+3)*128 + tok + 2*p);
      }
    }
#pragma unroll
    for (int j=0;j<TO;j++){
      float4 w = *reinterpret_cast<const float4*>(Ws + (g*TO+j)*K + k);
      ULL w0 = pk2(w.x,w.x), w1 = pk2(w.y,w.y), w2 = pk2(w.z,w.z), w3 = pk2(w.w,w.w);
#pragma unroll
      for (int p=0;p<PU;p++){
        FMA2(acc[j][p], a0[p], w0, acc[j][p]);
        FMA2(acc[j][p], a1[p], w1, acc[j][p]);
        FMA2(acc[j][p], a2[p], w2, acc[j][p]);
        FMA2(acc[j][p], a3[p], w3, acc[j][p]);
      }
    }
  }
#pragma unroll
  for (int j=0;j<TO;j++){
    if (TPT == 4){
      float2 v0 = upk(acc[j][0]);
      float2 v1 = upk(acc[j][PU-1]);
      if (RELU){
        v0.x=fmaxf(v0.x,0.f); v0.y=fmaxf(v0.y,0.f);
        v1.x=fmaxf(v1.x,0.f); v1.y=fmaxf(v1.y,0.f);
      }
      *reinterpret_cast<float4*>(C + (g*TO+j)*128 + tok) = make_float4(v0.x,v0.y,v1.x,v1.y);
    } else {
#pragma unroll
      for (int p=0;p<PU;p++){
        float2 v = upk(acc[j][p]);
        if (RELU){ v.x = fmaxf(v.x,0.f); v.y = fmaxf(v.y,0.f); }
        *reinterpret_cast<float2*>(C + (g*TO+j)*128 + tok + 2*p) = v;
      }
    }
  }
}

// h = LN(h + r), with up to two staging jobs overlapped into pass 1
__device__ __forceinline__ void add_ln(float* __restrict__ h,
                                       const float* __restrict__ r,
                                       const float* __restrict__ gs,
                                       const float* __restrict__ gb,
                                       float* __restrict__ aux, int tid,
                                       float* wdst0 = nullptr, const float* wsrc0 = nullptr, int n40 = 0,
                                       float* wdst1 = nullptr, const float* wsrc1 = nullptr, int n41 = 0)
{
  const int s = tid & 127, g = tid >> 7;
  float sum=0.f, sq=0.f;
#pragma unroll
  for (int d=16*g; d<16*g+16; d++){
    float x = h[d*128+s] + r[d*128+s];
    h[d*128+s] = x;
    sum += x; sq += x*x;
  }
  aux[g*128+s] = sum;
  aux[512 + g*128+s] = sq;
  if (wsrc0) stage(wdst0, wsrc0, n40, tid);
  if (wsrc1) stage(wdst1, wsrc1, n41, tid);
  __syncthreads();
  if (tid < 128){
    float S = aux[tid] + aux[128+tid] + aux[256+tid] + aux[384+tid];
    float Q = aux[512+tid] + aux[640+tid] + aux[768+tid] + aux[896+tid];
    float m = S * (1.f/64.f);
    float inv = rsqrtf(Q * (1.f/64.f) - m*m + EPS_);
    aux[1024+tid] = m;
    aux[1152+tid] = inv;
  }
  __syncthreads();
  {
    float m = aux[1024+s], inv = aux[1152+s];
#pragma unroll
    for (int d=16*g; d<16*g+16; d++){
      h[d*128+s] = (h[d*128+s] - m)*inv*__ldg(gs+d) + __ldg(gb+d);
    }
  }
}

__device__ __forceinline__ float dper(float diff, float L){
  float m = fmodf(diff + 0.5f*L, L);
  if (m < 0.f) m += L;
  return m - 0.5f*L;
}

__global__ void __launch_bounds__(512, 1)
ff_kernel(const int* __restrict__ q_lin_idx, const int* __restrict__ offs,
          const float* __restrict__ coords, const float* __restrict__ vals,
          const float* __restrict__ lg,
          const float* __restrict__ pw, const float* __restrict__ pb,
          const float* __restrict__ qw, const float* __restrict__ qbias,
          const float* __restrict__ ow, const float* __restrict__ obias,
          const float* __restrict__ l1s, const float* __restrict__ l1b,
          const float* __restrict__ f1w, const float* __restrict__ f1b,
          const float* __restrict__ f2w, const float* __restrict__ f2b,
          const float* __restrict__ l2s, const float* __restrict__ l2b,
          const float* __restrict__ hls, const float* __restrict__ hlb,
          const float* __restrict__ h1w, const float* __restrict__ h1b,
          const float* __restrict__ h2w, const float* __restrict__ h2b,
          float* __restrict__ out)
{
  extern __shared__ float sm[];
  float* h    = sm + OFF_H;
  float* qkv  = sm + OFF_QKV;
  float* att  = sm + OFF_ATT;
  float* aux  = sm + OFF_AUX;
  float* rs   = sm + OFF_RS;
  float* ps   = sm + OFF_PS;

  const int tid = threadIdx.x;
  const int b   = blockIdx.x;
  unsigned* attb0 = reinterpret_cast<unsigned*>(att);         // buffer 0 (4096 u32... 4096 fl)
  unsigned* attb1 = reinterpret_cast<unsigned*>(att + 4096);  // buffer 1

  // ---------------- Phase A: gather + input projection (+ stage layer-0 qkv W) ----------------
  {
    const int s = tid & 127, g = tid >> 7;
    int qi = __ldg(q_lin_idx + b);
    int i  = qi >> 13;
    int rr = qi & 8191;
    int j  = rr >> 6;
    int kk = rr & 63;
    int di = __ldg(offs + 3*s), dj = __ldg(offs + 3*s + 1), dk = __ldg(offs + 3*s + 2);
    int I = (i + di) & (NX_-1);
    int J = (j + dj) & (NY_-1);
    int T = min(max(kk + dk, 0), NT_-1);
    int nb = (I << 13) + (J << 6) + T;
    float qx = __ldg(coords + 3*qi), qy = __ldg(coords + 3*qi + 1), qt = __ldg(coords + 3*qi + 2);
    float nx = __ldg(coords + 3*nb), ny = __ldg(coords + 3*nb + 1), nt = __ldg(coords + 3*nb + 2);
    float g0 = expf(__ldg(lg+0)), g1 = expf(__ldg(lg+1)), g2 = expf(__ldg(lg+2));
    float f0 = dper(nx - qx, 2.0f) * g0;
    float f1 = dper(ny - qy, 2.0f) * g1;
    float f2 = (nt - qt) * g2;
    float f3 = __ldg(vals + 3*nb), f4 = __ldg(vals + 3*nb + 1), f5 = __ldg(vals + 3*nb + 2);
#pragma unroll
    for (int d = g*16; d < g*16 + 16; d++){
      float a = __ldg(pb + d);
      a += __ldg(pw + 6*d + 0)*f0 + __ldg(pw + 6*d + 1)*f1 + __ldg(pw + 6*d + 2)*f2
         + __ldg(pw + 6*d + 3)*f3 + __ldg(pw + 6*d + 4)*f4 + __ldg(pw + 6*d + 5)*f5;
      h[d*128 + s] = a;
    }
    stage(att, qw, 12288/4, tid);
  }
  __syncthreads();

  // ---------------- Phase B: 2 transformer layers ----------------
  for (int l = 0; l < 2; l++){
    gemm_sm<192,64,false,4>(h, att, qbias + l*192, qkv, tid);
    __syncthreads();

    // attention pipeline: QK(0), then per head [fold||combine] -> [AV ; QK(next)]
    qk_head(qkv, attb0, ps, 0, tid);
    __syncthreads();

    for (int hd = 0; hd < 4; hd++){
      unsigned* cur = (hd & 1) ? attb1 : attb0;
      unsigned* nxt = (hd & 1) ? attb0 : attb1;
      // fold (warps 0-3) || combine previous head (warps 4-15)
      if (tid < 128){
        float s0 = 0.f;
#pragma unroll
        for (int r2=0;r2<16;r2++) s0 += ps[r2*128 + tid];
        rs[tid] = s0;
      } else if (hd > 0){
        float4* ob = reinterpret_cast<float4*>(qkv + (hd-1)*16*128);
        const float4* p1 = reinterpret_cast<const float4*>(aux);
        const float4* p2 = reinterpret_cast<const float4*>(aux + 2048);
        const float4* p3 = reinterpret_cast<const float4*>(aux + 4096);
        for (int i = tid - 128; i < 512; i += 384){
          float4 o = ob[i], q1 = p1[i], q2 = p2[i], q3 = p3[i];
          o.x += q1.x + q2.x + q3.x;
          o.y += q1.y + q2.y + q3.y;
          o.z += q1.z + q2.z + q3.z;
          o.w += q1.w + q2.w + q3.w;
          ob[i] = o;
        }
      }
      __syncthreads();

      // AV(hd) then immediately QK(hd+1) — disjoint smem, no barrier between
      av_head(qkv, cur, rs, aux, hd, tid);
      if (hd < 3) qk_head(qkv, nxt, ps, hd+1, tid);
      __syncthreads();
    }

    // final combine for head 3 + stage out W into att buf0 region
    {
      float4* ob = reinterpret_cast<float4*>(qkv + 3*16*128);
      const float4* p1 = reinterpret_cast<const float4*>(aux);
      const float4* p2 = reinterpret_cast<const float4*>(aux + 2048);
      const float4* p3 = reinterpret_cast<const float4*>(aux + 4096);
      float4 o = ob[tid], q1 = p1[tid], q2 = p2[tid], q3 = p3[tid];
      o.x += q1.x + q2.x + q3.x;
      o.y += q1.y + q2.y + q3.y;
      o.z += q1.z + q2.z + q3.z;
      o.w += q1.w + q2.w + q3.w;
      ob[tid] = o;
      stage(att, ow + l*64*64, 4096/4, tid);
    }
    __syncthreads();

    // out gemm: W in att[0:4096), C -> att[4096:12288)
    gemm_sm<64,64,false,2>(qkv, att, obias + l*64, att + 4096, tid);
    __syncthreads();
    add_ln(h, att + 4096, l1s + l*64, l1b + l*64, aux, tid,
           qkv,        f1w + l*128*64, 8192/4,
           qkv + 8192, f2w + l*64*128, 8192/4);
    __syncthreads();
    gemm_sm<128,64,true,2>(h, qkv, f1b + l*128, att, tid);
    __syncthreads();
    gemm_sm<64,128,false,2>(att, qkv + 8192, f2b + l*64, qkv, tid);
    __syncthreads();
    if (l == 0){
      add_ln(h, qkv, l2s, l2b, aux, tid, att, qw + 12288, 12288/4);
    } else {
      add_ln(h, qkv, l2s + 64, l2b + 64, aux, tid);
    }
    __syncthreads();
  }

  // ---------------- Phase C ----------------
  {
    const int d = tid & 63, oc = tid >> 6;
    float s0 = 0.f;
#pragma unroll
    for (int t = oc*16; t < oc*16 + 16; t++) s0 += h[d*128 + t];
    aux[oc*64 + d] = s0;
  }
  __syncthreads();
  if (tid < 64){
    float hm = 0.f;
#pragma unroll
    for (int o2=0;o2<8;o2++) hm += aux[o2*64 + tid];
    aux[512 + tid] = hm * (1.0f/128.0f);
  }
  __syncthreads();
  if (tid < 32){
    float a = aux[512 + tid], c = aux[512 + 32 + tid];
    float sum = a + c, sq = a*a + c*c;
#pragma unroll
    for (int off=16; off; off>>=1){
      sum += __shfl_xor_sync(0xffffffffu, sum, off);
      sq  += __shfl_xor_sync(0xffffffffu, sq,  off);
    }
    if (tid == 0){
      float m = sum * (1.f/64.f);
      aux[576] = m;
      aux[577] = rsqrtf(sq * (1.f/64.f) - m*m + EPS_);
    }
  }
  __syncthreads();
  if (tid < 64){
    float m = aux[576], inv = aux[577];
    aux[640 + tid] = (aux[512+tid] - m)*inv*__ldg(hls+tid) + __ldg(hlb+tid);
  }
  __syncthreads();
  if (tid < 64){
    float acc = __ldg(h1b + tid);
#pragma unroll 8
    for (int k=0;k<64;k++) acc += aux[640+k]*__ldg(h1w + tid*64 + k);
    aux[704 + tid] = 0.5f*acc*(1.0f + erff(acc*0.70710678118654752f));
  }
  __syncthreads();
  if (tid < 3){
    float acc = __ldg(h2b + tid);
#pragma unroll 8
    for (int k=0;k<64;k++) acc += aux[704+k]*__ldg(h2w + tid*64 + k);
    out[b*3 + tid] = acc;
  }
}

extern "C" void kernel_launch(void* const* d_in, const int* in_sizes, int n_in,
                              void* d_out, int out_size)
{
  const int*   qli    = (const int*)  d_in[0];
  const int*   offs   = (const int*)  d_in[1];
  const float* coords = (const float*)d_in[2];
  const float* vals   = (const float*)d_in[3];
  const float* lg     = (const float*)d_in[4];
  const float* pw     = (const float*)d_in[5];
  const float* pb     = (const float*)d_in[6];
  const float* qw     = (const float*)d_in[7];
  const float* qb     = (const float*)d_in[8];
  const float* ow     = (const float*)d_in[9];
  const float* ob     = (const float*)d_in[10];
  const float* l1s    = (const float*)d_in[11];
  const float* l1b    = (const float*)d_in[12];
  const float* f1w    = (const float*)d_in[13];
  const float* f1b    = (const float*)d_in[14];
  const float* f2w    = (const float*)d_in[15];
  const float* f2b    = (const float*)d_in[16];
  const float* l2s    = (const float*)d_in[17];
  const float* l2b    = (const float*)d_in[18];
  const float* hls    = (const float*)d_in[19];
  const float* hlb    = (const float*)d_in[20];
  const float* h1w    = (const float*)d_in[21];
  const float* h1b    = (const float*)d_in[22];
  const float* h2w    = (const float*)d_in[23];
  const float* h2b    = (const float*)d_in[24];
  float* out = (float*)d_out;
  const int B = in_sizes[0];

  cudaFuncSetAttribute(ff_kernel, cudaFuncAttributeMaxDynamicSharedMemorySize,
                       SMEM_FLOATS * (int)sizeof(float));
  ff_kernel<<<B, 512, SMEM_FLOATS * sizeof(float)>>>(
      qli, offs, coords, vals, lg, pw, pb, qw, qb, ow, ob,
      l1s, l1b, f1w, f1b, f2w, f2b, l2s, l2b,
      hls, hlb, h1w, h1b, h2w, h2b, out);
}

// round 17
// speedup vs baseline: 1.0201x; 1.0019x over previous
#include <cuda_runtime.h>

typedef unsigned long long ULL;

__device__ __forceinline__ ULL pk2(float lo, float hi){
  ULL r; asm("mov.b64 %0, {%1,%2};" : "=l"(r) : "f"(lo), "f"(hi)); return r;
}
__device__ __forceinline__ float2 upk(ULL v){
  float2 r; asm("mov.b64 {%0,%1}, %2;" : "=f"(r.x), "=f"(r.y) : "l"(v)); return r;
}
#define FMA2(d,a,bb,c) asm("fma.rn.f32x2 %0, %1, %2, %3;" : "=l"(d) : "l"(a), "l"(bb), "l"(c))
#define MUL2(d,a,bb)   asm("mul.rn.f32x2 %0, %1, %2;"     : "=l"(d) : "l"(a), "l"(bb))
#define ADD2(d,a,bb)   asm("add.rn.f32x2 %0, %1, %2;"     : "=l"(d) : "l"(a), "l"(bb))

constexpr int NX_ = 128, NY_ = 128, NT_ = 64;
constexpr float EPS_ = 1e-5f;

constexpr int OFF_H   = 0;         // h[64][128]
constexpr int OFF_QKV = 8192;      // qkv[192][128]; also ff1 W (8192) + ff2 W (8192)
constexpr int OFF_ATT = 32768;     // att bf16 DOUBLE buffer (2x4096 fl); staged qkv W; out W + C; ff hidden
constexpr int OFF_AUX = 49152;     // AV partials (3*2048) / LN scratch
constexpr int OFF_RS  = 55296;     // 128 row sums
constexpr int OFF_PS  = 55808;     // QK row partial sums [16][128]
constexpr int SMEM_FLOATS = 57856; // 231,424 bytes (max 232,448)

__device__ __forceinline__ void stage(float* __restrict__ dst,
                                      const float* __restrict__ src,
                                      int n4, int tid)
{
  const float4* s = reinterpret_cast<const float4*>(src);
  float4* d = reinterpret_cast<float4*>(dst);
  for (int i = tid; i < n4; i += 512) d[i] = s[i];
}

// QK^T + fused exp (packed degree-5 Taylor; |t|<=~0.5) + row partial sums; att bf16x2
__device__ __forceinline__ void qk_head(const float* __restrict__ qkv,
                                        unsigned* __restrict__ attbuf,
                                        float* __restrict__ ps, int hd, int tid)
{
  const float* qb2 = qkv + (hd*16)*128;
  const float* kb  = qkv + (64 + hd*16)*128;
  const int tx = tid & 31;   // sq tile of 4 (lane-contiguous)
  const int ty = tid >> 5;   // sk tile of 8 (warp-uniform)
  ULL acc[8][2];
  ULL z = pk2(0.f, 0.f);
#pragma unroll
  for (int jj=0;jj<8;jj++){ acc[jj][0]=z; acc[jj][1]=z; }
#pragma unroll 4
  for (int di=0; di<16; di++){
    float4 qf = *reinterpret_cast<const float4*>(qb2 + di*128 + 4*tx);
    ULL q0 = pk2(qf.x,qf.y), q1 = pk2(qf.z,qf.w);
    float4 k0 = *reinterpret_cast<const float4*>(kb + di*128 + 8*ty);
    float4 k1 = *reinterpret_cast<const float4*>(kb + di*128 + 8*ty + 4);
    float kvv[8] = {k0.x,k0.y,k0.z,k0.w,k1.x,k1.y,k1.z,k1.w};
#pragma unroll
    for (int jj=0;jj<8;jj++){
      ULL kd = pk2(kvv[jj], kvv[jj]);
      FMA2(acc[jj][0], q0, kd, acc[jj][0]);
      FMA2(acc[jj][1], q1, kd, acc[jj][1]);
    }
  }
  const ULL qtr = pk2(0.25f, 0.25f);
  const ULL c5 = pk2(8.3333333e-3f, 8.3333333e-3f);   // 1/120
  const ULL c4 = pk2(4.1666667e-2f, 4.1666667e-2f);   // 1/24
  const ULL c3 = pk2(1.6666667e-1f, 1.6666667e-1f);   // 1/6
  const ULL c2 = pk2(0.5f, 0.5f);
  const ULL c1 = pk2(1.0f, 1.0f);
  ULL ps0 = pk2(0.f,0.f), ps1 = pk2(0.f,0.f);
#pragma unroll
  for (int jj=0;jj<8;jj++){
    ULL t0, t1;
    MUL2(t0, acc[jj][0], qtr);
    MUL2(t1, acc[jj][1], qtr);
    ULL e0 = c5, e1 = c5;
    FMA2(e0, e0, t0, c4);  FMA2(e1, e1, t1, c4);
    FMA2(e0, e0, t0, c3);  FMA2(e1, e1, t1, c3);
    FMA2(e0, e0, t0, c2);  FMA2(e1, e1, t1, c2);
    FMA2(e0, e0, t0, c1);  FMA2(e1, e1, t1, c1);
    FMA2(e0, e0, t0, c1);  FMA2(e1, e1, t1, c1);
    ADD2(ps0, ps0, e0);
    ADD2(ps1, ps1, e1);
    float2 f0 = upk(e0);
    float2 f1 = upk(e1);
    unsigned p0, p1;
    asm("cvt.rn.bf16x2.f32 %0, %1, %2;" : "=r"(p0) : "f"(f0.y), "f"(f0.x));
    asm("cvt.rn.bf16x2.f32 %0, %1, %2;" : "=r"(p1) : "f"(f1.y), "f"(f1.x));
    *reinterpret_cast<uint2*>(attbuf + (8*ty+jj)*64 + 2*tx) = make_uint2(p0, p1);
  }
  float2 a = upk(ps0);
  float2 b2 = upk(ps1);
  *reinterpret_cast<float4*>(ps + ty*128 + 4*tx) = make_float4(a.x, a.y, b2.x, b2.y);
}

// AV for head hd: reads attbuf (bf16x2) + rs; writes o-slice (hf0) / aux partials
__device__ __forceinline__ void av_head(float* __restrict__ qkv,
                                        const unsigned* __restrict__ attbuf,
                                        const float* __restrict__ rs,
                                        float* __restrict__ aux, int hd, int tid)
{
  const int pg = tid & 63;        // sq pair: sq = 2*pg
  const int dq = (tid>>6) & 1;    // dv octet
  const int hf = tid >> 7;        // sk quarter
  const float* vb = qkv + (128 + hd*16 + 8*dq)*128;
  ULL acc[8];
  ULL z = pk2(0.f,0.f);
#pragma unroll
  for (int r2=0;r2<8;r2++) acc[r2]=z;
  for (int sk0 = hf*32; sk0 < hf*32 + 32; sk0 += 4){
    float4 vr[8];
#pragma unroll
    for (int r2=0;r2<8;r2++)
      vr[r2] = *reinterpret_cast<const float4*>(vb + r2*128 + sk0);
    unsigned u0 = attbuf[(sk0  )*64 + pg];
    unsigned u1 = attbuf[(sk0+1)*64 + pg];
    unsigned u2 = attbuf[(sk0+2)*64 + pg];
    unsigned u3 = attbuf[(sk0+3)*64 + pg];
    ULL a0 = pk2(__uint_as_float(u0 << 16), __uint_as_float(u0 & 0xFFFF0000u));
    ULL a1 = pk2(__uint_as_float(u1 << 16), __uint_as_float(u1 & 0xFFFF0000u));
    ULL a2 = pk2(__uint_as_float(u2 << 16), __uint_as_float(u2 & 0xFFFF0000u));
    ULL a3 = pk2(__uint_as_float(u3 << 16), __uint_as_float(u3 & 0xFFFF0000u));
#pragma unroll
    for (int r2=0;r2<8;r2++){
      FMA2(acc[r2], a0, pk2(vr[r2].x, vr[r2].x), acc[r2]);
      FMA2(acc[r2], a1, pk2(vr[r2].y, vr[r2].y), acc[r2]);
      FMA2(acc[r2], a2, pk2(vr[r2].z, vr[r2].z), acc[r2]);
      FMA2(acc[r2], a3, pk2(vr[r2].w, vr[r2].w), acc[r2]);
    }
  }
  ULL sv = *reinterpret_cast<const ULL*>(rs + 2*pg);
  float2 sf = upk(sv);
  ULL iv = pk2(1.0f/sf.x, 1.0f/sf.y);
  float* dst = (hf==0) ? (qkv + (hd*16 + 8*dq)*128)
                       : (aux + (hf-1)*2048 + 8*dq*128);
#pragma unroll
  for (int r2=0;r2<8;r2++){
    MUL2(acc[r2], acc[r2], iv);
    *reinterpret_cast<ULL*>(dst + r2*128 + 2*pg) = acc[r2];
  }
}

// C[o][s] = act( sum_k A[k][s]*Ws[o*K+k] + Bv[o] ); Ws in SHARED (uniform broadcast reads)
template<int OUT, int K, bool RELU, int TPT>
__device__ __forceinline__ void gemm_sm(const float* __restrict__ A,
                                        const float* __restrict__ Ws,
                                        const float* __restrict__ Bv,
                                        float* __restrict__ C, int tid)
{
  constexpr int NTG = 128/TPT;
  constexpr int NOG = 512/NTG;
  constexpr int TO  = OUT/NOG;
  constexpr int PU  = TPT/2;
  const int tx  = tid & (NTG-1);
  const int g   = tid / NTG;        // warp-uniform
  const int tok = TPT*tx;
  ULL acc[TO][PU];
#pragma unroll
  for (int j=0;j<TO;j++){
    float b = __ldg(Bv + g*TO + j);
    ULL bb = pk2(b,b);
#pragma unroll
    for (int p=0;p<PU;p++) acc[j][p] = bb;
  }
#pragma unroll 2
  for (int k=0;k<K;k+=4){
    ULL a0[PU], a1[PU], a2[PU], a3[PU];
    if (TPT == 4){
      float4 f0 = *reinterpret_cast<const float4*>(A + (k  )*128 + tok);
      float4 f1 = *reinterpret_cast<const float4*>(A + (k+1)*128 + tok);
      float4 f2 = *reinterpret_cast<const float4*>(A + (k+2)*128 + tok);
      float4 f3 = *reinterpret_cast<const float4*>(A + (k+3)*128 + tok);
      a0[0]=pk2(f0.x,f0.y); a0[PU-1]=pk2(f0.z,f0.w);
      a1[0]=pk2(f1.x,f1.y); a1[PU-1]=pk2(f1.z,f1.w);
      a2[0]=pk2(f2.x,f2.y); a2[PU-1]=pk2(f2.z,f2.w);
      a3[0]=pk2(f3.x,f3.y); a3[PU-1]=pk2(f3.z,f3.w);
    } else {
#pragma unroll
      for (int p=0;p<PU;p++){
        a0[p] = *reinterpret_cast<const ULL*>(A + (k  )*128 + tok + 2*p);
        a1[p] = *reinterpret_cast<const ULL*>(A + (k+1)*128 + tok + 2*p);
        a2[p] = *reinterpret_cast<const ULL*>(A + (k+2)*128 + tok + 2*p);
        a3[p] = *reinterpret_cast<const ULL*>(A + (k+3)*128 + tok + 2*p);
      }
    }
#pragma unroll
    for (int j=0;j<TO;j++){
      float4 w = *reinterpret_cast<const float4*>(Ws + (g*TO+j)*K + k);
      ULL w0 = pk2(w.x,w.x), w1 = pk2(w.y,w.y), w2 = pk2(w.z,w.z), w3 = pk2(w.w,w.w);
#pragma unroll
      for (int p=0;p<PU;p++){
        FMA2(acc[j][p], a0[p], w0, acc[j][p]);
        FMA2(acc[j][p], a1[p], w1, acc[j][p]);
        FMA2(acc[j][p], a2[p], w2, acc[j][p]);
        FMA2(acc[j][p], a3[p], w3, acc[j][p]);
      }
    }
  }
#pragma unroll
  for (int j=0;j<TO;j++){
    if (TPT == 4){
      float2 v0 = upk(acc[j][0]);
      float2 v1 = upk(acc[j][PU-1]);
      if (RELU){
        v0.x=fmaxf(v0.x,0.f); v0.y=fmaxf(v0.y,0.f);
        v1.x=fmaxf(v1.x,0.f); v1.y=fmaxf(v1.y,0.f);
      }
      *reinterpret_cast<float4*>(C + (g*TO+j)*128 + tok) = make_float4(v0.x,v0.y,v1.x,v1.y);
    } else {
#pragma unroll
      for (int p=0;p<PU;p++){
        float2 v = upk(acc[j][p]);
        if (RELU){ v.x = fmaxf(v.x,0.f); v.y = fmaxf(v.y,0.f); }
        *reinterpret_cast<float2*>(C + (g*TO+j)*128 + tok + 2*p) = v;
      }
    }
  }
}

// h = LN(h + r), with up to two staging jobs overlapped into pass 1
__device__ __forceinline__ void add_ln(float* __restrict__ h,
                                       const float* __restrict__ r,
                                       const float* __restrict__ gs,
                                       const float* __restrict__ gb,
                                       float* __restrict__ aux, int tid,
                                       float* wdst0 = nullptr, const float* wsrc0 = nullptr, int n40 = 0,
                                       float* wdst1 = nullptr, const float* wsrc1 = nullptr, int n41 = 0)
{
  const int s = tid & 127, g = tid >> 7;
  float sum=0.f, sq=0.f;
#pragma unroll
  for (int d=16*g; d<16*g+16; d++){
    float x = h[d*128+s] + r[d*128+s];
    h[d*128+s] = x;
    sum += x; sq += x*x;
  }
  aux[g*128+s] = sum;
  aux[512 + g*128+s] = sq;
  if (wsrc0) stage(wdst0, wsrc0, n40, tid);
  if (wsrc1) stage(wdst1, wsrc1, n41, tid);
  __syncthreads();
  if (tid < 128){
    float S = aux[tid] + aux[128+tid] + aux[256+tid] + aux[384+tid];
    float Q = aux[512+tid] + aux[640+tid] + aux[768+tid] + aux[896+tid];
    float m = S * (1.f/64.f);
    float inv = rsqrtf(Q * (1.f/64.f) - m*m + EPS_);
    aux[1024+tid] = m;
    aux[1152+tid] = inv;
  }
  __syncthreads();
  {
    float m = aux[1024+s], inv = aux[1152+s];
#pragma unroll
    for (int d=16*g; d<16*g+16; d++){
      h[d*128+s] = (h[d*128+s] - m)*inv*__ldg(gs+d) + __ldg(gb+d);
    }
  }
}

__device__ __forceinline__ float dper(float diff, float L){
  float m = fmodf(diff + 0.5f*L, L);
  if (m < 0.f) m += L;
  return m - 0.5f*L;
}

__global__ void __launch_bounds__(512, 1)
ff_kernel(const int* __restrict__ q_lin_idx, const int* __restrict__ offs,
          const float* __restrict__ coords, const float* __restrict__ vals,
          const float* __restrict__ lg,
          const float* __restrict__ pw, const float* __restrict__ pb,
          const float* __restrict__ qw, const float* __restrict__ qbias,
          const float* __restrict__ ow, const float* __restrict__ obias,
          const float* __restrict__ l1s, const float* __restrict__ l1b,
          const float* __restrict__ f1w, const float* __restrict__ f1b,
          const float* __restrict__ f2w, const float* __restrict__ f2b,
          const float* __restrict__ l2s, const float* __restrict__ l2b,
          const float* __restrict__ hls, const float* __restrict__ hlb,
          const float* __restrict__ h1w, const float* __restrict__ h1b,
          const float* __restrict__ h2w, const float* __restrict__ h2b,
          float* __restrict__ out)
{
  extern __shared__ float sm[];
  float* h    = sm + OFF_H;
  float* qkv  = sm + OFF_QKV;
  float* att  = sm + OFF_ATT;
  float* aux  = sm + OFF_AUX;
  float* rs   = sm + OFF_RS;
  float* ps   = sm + OFF_PS;

  const int tid = threadIdx.x;
  const int b   = blockIdx.x;
  unsigned* attb0 = reinterpret_cast<unsigned*>(att);         // buffer 0
  unsigned* attb1 = reinterpret_cast<unsigned*>(att + 4096);  // buffer 1

  // ---------------- Phase A: gather + input projection (+ stage layer-0 qkv W) ----------------
  {
    const int s = tid & 127, g = tid >> 7;
    int qi = __ldg(q_lin_idx + b);
    int i  = qi >> 13;
    int rr = qi & 8191;
    int j  = rr >> 6;
    int kk = rr & 63;
    int di = __ldg(offs + 3*s), dj = __ldg(offs + 3*s + 1), dk = __ldg(offs + 3*s + 2);
    int I = (i + di) & (NX_-1);
    int J = (j + dj) & (NY_-1);
    int T = min(max(kk + dk, 0), NT_-1);
    int nb = (I << 13) + (J << 6) + T;
    float qx = __ldg(coords + 3*qi), qy = __ldg(coords + 3*qi + 1), qt = __ldg(coords + 3*qi + 2);
    float nx = __ldg(coords + 3*nb), ny = __ldg(coords + 3*nb + 1), nt = __ldg(coords + 3*nb + 2);
    float g0 = expf(__ldg(lg+0)), g1 = expf(__ldg(lg+1)), g2 = expf(__ldg(lg+2));
    float f0 = dper(nx - qx, 2.0f) * g0;
    float f1 = dper(ny - qy, 2.0f) * g1;
    float f2 = (nt - qt) * g2;
    float f3 = __ldg(vals + 3*nb), f4 = __ldg(vals + 3*nb + 1), f5 = __ldg(vals + 3*nb + 2);
#pragma unroll
    for (int d = g*16; d < g*16 + 16; d++){
      float a = __ldg(pb + d);
      a += __ldg(pw + 6*d + 0)*f0 + __ldg(pw + 6*d + 1)*f1 + __ldg(pw + 6*d + 2)*f2
         + __ldg(pw + 6*d + 3)*f3 + __ldg(pw + 6*d + 4)*f4 + __ldg(pw + 6*d + 5)*f5;
      h[d*128 + s] = a;
    }
    stage(att, qw, 12288/4, tid);
  }
  __syncthreads();

  // ---------------- Phase B: 2 transformer layers ----------------
  for (int l = 0; l < 2; l++){
    gemm_sm<192,64,false,4>(h, att, qbias + l*192, qkv, tid);
    __syncthreads();

    // attention pipeline: QK(0), then per head [fold||combine] -> [AV ; QK(next)]
    qk_head(qkv, attb0, ps, 0, tid);
    __syncthreads();

    for (int hd = 0; hd < 4; hd++){
      unsigned* cur = (hd & 1) ? attb1 : attb0;
      unsigned* nxt = (hd & 1) ? attb0 : attb1;
      // fold (warps 0-3) || combine previous head (warps 4-15)
      if (tid < 128){
        float s0 = 0.f;
#pragma unroll
        for (int r2=0;r2<16;r2++) s0 += ps[r2*128 + tid];
        rs[tid] = s0;
      } else if (hd > 0){
        float4* ob = reinterpret_cast<float4*>(qkv + (hd-1)*16*128);
        const float4* p1 = reinterpret_cast<const float4*>(aux);
        const float4* p2 = reinterpret_cast<const float4*>(aux + 2048);
        const float4* p3 = reinterpret_cast<const float4*>(aux + 4096);
        for (int i = tid - 128; i < 512; i += 384){
          float4 o = ob[i], q1 = p1[i], q2 = p2[i], q3 = p3[i];
          o.x += q1.x + q2.x + q3.x;
          o.y += q1.y + q2.y + q3.y;
          o.z += q1.z + q2.z + q3.z;
          o.w += q1.w + q2.w + q3.w;
          ob[i] = o;
        }
      }
      __syncthreads();

      // AV(hd) then immediately QK(hd+1) — disjoint smem, no barrier between
      av_head(qkv, cur, rs, aux, hd, tid);
      if (hd < 3) qk_head(qkv, nxt, ps, hd+1, tid);
      __syncthreads();
    }

    // final combine for head 3 + stage out W into att buf0 region
    {
      float4* ob = reinterpret_cast<float4*>(qkv + 3*16*128);
      const float4* p1 = reinterpret_cast<const float4*>(aux);
      const float4* p2 = reinterpret_cast<const float4*>(aux + 2048);
      const float4* p3 = reinterpret_cast<const float4*>(aux + 4096);
      float4 o = ob[tid], q1 = p1[tid], q2 = p2[tid], q3 = p3[tid];
      o.x += q1.x + q2.x + q3.x;
      o.y += q1.y + q2.y + q3.y;
      o.z += q1.z + q2.z + q3.z;
      o.w += q1.w + q2.w + q3.w;
      ob[tid] = o;
      stage(att, ow + l*64*64, 4096/4, tid);
    }
    __syncthreads();

    // out gemm: W in att[0:4096), C -> att[4096:12288)
    gemm_sm<64,64,false,2>(qkv, att, obias + l*64, att + 4096, tid);
    __syncthreads();
    add_ln(h, att + 4096, l1s + l*64, l1b + l*64, aux, tid,
           qkv,        f1w + l*128*64, 8192/4,
           qkv + 8192, f2w + l*64*128, 8192/4);
    __syncthreads();
    gemm_sm<128,64,true,2>(h, qkv, f1b + l*128, att, tid);
    __syncthreads();
    gemm_sm<64,128,false,2>(att, qkv + 8192, f2b + l*64, qkv, tid);
    __syncthreads();
    if (l == 0){
      add_ln(h, qkv, l2s, l2b, aux, tid, att, qw + 12288, 12288/4);
    } else {
      add_ln(h, qkv, l2s + 64, l2b + 64, aux, tid);
    }
    __syncthreads();
  }

  // ---------------- Phase C ----------------
  {
    const int d = tid & 63, oc = tid >> 6;
    float s0 = 0.f;
#pragma unroll
    for (int t = oc*16; t < oc*16 + 16; t++) s0 += h[d*128 + t];
    aux[oc*64 + d] = s0;
  }
  __syncthreads();
  if (tid < 64){
    float hm = 0.f;
#pragma unroll
    for (int o2=0;o2<8;o2++) hm += aux[o2*64 + tid];
    aux[512 + tid] = hm * (1.0f/128.0f);
  }
  __syncthreads();
  if (tid < 32){
    float a = aux[512 + tid], c = aux[512 + 32 + tid];
    float sum = a + c, sq = a*a + c*c;
#pragma unroll
    for (int off=16; off; off>>=1){
      sum += __shfl_xor_sync(0xffffffffu, sum, off);
      sq  += __shfl_xor_sync(0xffffffffu, sq,  off);
    }
    if (tid == 0){
      float m = sum * (1.f/64.f);
      aux[576] = m;
      aux[577] = rsqrtf(sq * (1.f/64.f) - m*m + EPS_);
    }
  }
  __syncthreads();
  if (tid < 64){
    float m = aux[576], inv = aux[577];
    aux[640 + tid] = (aux[512+tid] - m)*inv*__ldg(hls+tid) + __ldg(hlb+tid);
  }
  __syncthreads();
  if (tid < 64){
    float acc = __ldg(h1b + tid);
#pragma unroll 8
    for (int k=0;k<64;k++) acc += aux[640+k]*__ldg(h1w + tid*64 + k);
    aux[704 + tid] = 0.5f*acc*(1.0f + erff(acc*0.70710678118654752f));
  }
  __syncthreads();
  if (tid < 3){
    float acc = __ldg(h2b + tid);
#pragma unroll 8
    for (int k=0;k<64;k++) acc += aux[704+k]*__ldg(h2w + tid*64 + k);
    out[b*3 + tid] = acc;
  }
}

extern "C" void kernel_launch(void* const* d_in, const int* in_sizes, int n_in,
                              void* d_out, int out_size)
{
  const int*   qli    = (const int*)  d_in[0];
  const int*   offs   = (const int*)  d_in[1];
  const float* coords = (const float*)d_in[2];
  const float* vals   = (const float*)d_in[3];
  const float* lg     = (const float*)d_in[4];
  const float* pw     = (const float*)d_in[5];
  const float* pb     = (const float*)d_in[6];
  const float* qw     = (const float*)d_in[7];
  const float* qb     = (const float*)d_in[8];
  const float* ow     = (const float*)d_in[9];
  const float* ob     = (const float*)d_in[10];
  const float* l1s    = (const float*)d_in[11];
  const float* l1b    = (const float*)d_in[12];
  const float* f1w    = (const float*)d_in[13];
  const float* f1b    = (const float*)d_in[14];
  const float* f2w    = (const float*)d_in[15];
  const float* f2b    = (const float*)d_in[16];
  const float* l2s    = (const float*)d_in[17];
  const float* l2b    = (const float*)d_in[18];
  const float* hls    = (const float*)d_in[19];
  const float* hlb    = (const float*)d_in[20];
  const float* h1w    = (const float*)d_in[21];
  const float* h1b    = (const float*)d_in[22];
  const float* h2w    = (const float*)d_in[23];
  const float* h2b    = (const float*)d_in[24];
  float* out = (float*)d_out;
  const int B = in_sizes[0];

  cudaFuncSetAttribute(ff_kernel, cudaFuncAttributeMaxDynamicSharedMemorySize,
                       SMEM_FLOATS * (int)sizeof(float));
  ff_kernel<<<B, 512, SMEM_FLOATS * sizeof(float)>>>(
      qli, offs, coords, vals, lg, pw, pb, qw, qb, ow, ob,
      l1s, l1b, f1w, f1b, f2w, f2b, l2s, l2b,
      hls, hlb, h1w, h1b, h2w, h2b, out);
}